// round 3
// baseline (speedup 1.0000x reference)
#include <cuda_runtime.h>
#include <cuda_bf16.h>
#include <stdint.h>

// ============================================================================
// ChaosLanguageModel: embed-mean -> 10-tick stochastic spiking -> readout
// Replicates JAX threefry2x32 RNG bit-exactly (partitionable path).
// R3: phaseA gather made 4-lane cooperative (one float4 per lane per token)
// to cut L1tex wavefronts 4x (R2 was L1=82% wavefront-bound at 57us).
// ============================================================================

#define EMBED 16
#define HIDDEN 64
#define TICKS 10
#define SEQLEN 200
#define TOKITER (SEQLEN / 8)   // 25

__device__ float g_cur[16384 * HIDDEN];   // drive current per neuron
__device__ float g_spk[16384 * HIDDEN];   // fallback spike buffer

// ---------------------------------------------------------------------------
// threefry2x32 (JAX rotation schedule)
// ---------------------------------------------------------------------------
__device__ __forceinline__ void tf2x32_dev(uint32_t k0, uint32_t k1,
                                           uint32_t x0, uint32_t x1,
                                           uint32_t& o0, uint32_t& o1) {
    uint32_t k2 = k0 ^ k1 ^ 0x1BD11BDAu;
#define TF_RND(r) { x0 += x1; x1 = __funnelshift_l(x1, x1, (r)); x1 ^= x0; }
    x0 += k0; x1 += k1;
    TF_RND(13) TF_RND(15) TF_RND(26) TF_RND(6)
    x0 += k1; x1 += k2 + 1u;
    TF_RND(17) TF_RND(29) TF_RND(16) TF_RND(24)
    x0 += k2; x1 += k0 + 2u;
    TF_RND(13) TF_RND(15) TF_RND(26) TF_RND(6)
    x0 += k0; x1 += k1 + 3u;
    TF_RND(17) TF_RND(29) TF_RND(16) TF_RND(24)
    x0 += k1; x1 += k2 + 4u;
    TF_RND(13) TF_RND(15) TF_RND(26) TF_RND(6)
    x0 += k2; x1 += k0 + 5u;
#undef TF_RND
    o0 = x0; o1 = x1;
}

static inline uint32_t rotl_h(uint32_t x, int r) { return (x << r) | (x >> (32 - r)); }
static void tf2x32_host(uint32_t k0, uint32_t k1, uint32_t x0, uint32_t x1,
                        uint32_t* o0, uint32_t* o1) {
    uint32_t k2 = k0 ^ k1 ^ 0x1BD11BDAu;
#define TF_RND(r) { x0 += x1; x1 = rotl_h(x1, (r)); x1 ^= x0; }
    x0 += k0; x1 += k1;
    TF_RND(13) TF_RND(15) TF_RND(26) TF_RND(6)
    x0 += k1; x1 += k2 + 1u;
    TF_RND(17) TF_RND(29) TF_RND(16) TF_RND(24)
    x0 += k2; x1 += k0 + 2u;
    TF_RND(13) TF_RND(15) TF_RND(26) TF_RND(6)
    x0 += k0; x1 += k1 + 3u;
    TF_RND(17) TF_RND(29) TF_RND(16) TF_RND(24)
    x0 += k1; x1 += k2 + 4u;
    TF_RND(13) TF_RND(15) TF_RND(26) TF_RND(6)
    x0 += k2; x1 += k0 + 5u;
#undef TF_RND
    *o0 = x0; *o1 = x1;
}

// ---------------------------------------------------------------------------
// XLA erf_inv (f32, Giles polynomial)
// ---------------------------------------------------------------------------
__device__ __forceinline__ float erfinv_xla(float x) {
    float t = __fmul_rn(x, x);
    float w = -log1pf(-t);
    float p;
    if (w < 5.0f) {
        w = __fsub_rn(w, 2.5f);
        p = 2.81022636e-08f;
        p = __fadd_rn(__fmul_rn(p, w),  3.43273939e-07f);
        p = __fadd_rn(__fmul_rn(p, w), -3.5233877e-06f);
        p = __fadd_rn(__fmul_rn(p, w), -4.39150654e-06f);
        p = __fadd_rn(__fmul_rn(p, w),  0.00021858087f);
        p = __fadd_rn(__fmul_rn(p, w), -0.00125372503f);
        p = __fadd_rn(__fmul_rn(p, w), -0.00417768164f);
        p = __fadd_rn(__fmul_rn(p, w),  0.246640727f);
        p = __fadd_rn(__fmul_rn(p, w),  1.50140941f);
    } else {
        w = __fsub_rn(__fsqrt_rn(w), 3.0f);
        p = -0.000200214257f;
        p = __fadd_rn(__fmul_rn(p, w),  0.000100950558f);
        p = __fadd_rn(__fmul_rn(p, w),  0.00134934322f);
        p = __fadd_rn(__fmul_rn(p, w), -0.00367342844f);
        p = __fadd_rn(__fmul_rn(p, w),  0.00573950773f);
        p = __fadd_rn(__fmul_rn(p, w), -0.0076224613f);
        p = __fadd_rn(__fmul_rn(p, w),  0.00943887047f);
        p = __fadd_rn(__fmul_rn(p, w),  1.00167406f);
        p = __fadd_rn(__fmul_rn(p, w),  2.83297682f);
    }
    return __fmul_rn(p, x);
}

// ---------------------------------------------------------------------------
// Phase A (R3): warp-per-row, 4-lane cooperative gather.
//   lane = 4*g + c : group g (0..7) owns tokens j%8==g, chunk c owns dims 4c..4c+3
//   One warp LDG.128 covers 8 tokens' 64B rows -> <=8 L1 wavefronts.
// ---------------------------------------------------------------------------
__global__ void __launch_bounds__(256)
phaseA_kernel(const int* __restrict__ tokens,
              const float* __restrict__ embed,
              const float* __restrict__ Wc,
              const float* __restrict__ bc,
              float* __restrict__ cur, int B) {
    __shared__ float sWc[HIDDEN * EMBED];   // 4 KB
    __shared__ float sbc[HIDDEN];
    __shared__ float savg[8][EMBED];        // per-warp avg broadcast

    int tid = threadIdx.x;
    for (int i = tid; i < HIDDEN * EMBED; i += 256) sWc[i] = Wc[i];
    if (tid < HIDDEN) sbc[tid] = bc[tid];
    __syncthreads();

    int warp = (blockIdx.x * 256 + tid) >> 5;
    int wib  = (tid >> 5);
    int lane = tid & 31;
    if (warp >= B) return;

    int g = lane >> 2;      // token subgroup 0..7
    int c = lane & 3;       // dim chunk 0..3

    const int* trow = tokens + (size_t)warp * SEQLEN;

    // preload this lane's 25 tokens (independent loads, high MLP)
    int tks[TOKITER];
    #pragma unroll
    for (int i = 0; i < TOKITER; i++)
        tks[i] = __ldg(trow + i * 8 + g);

    float ax = 0.f, ay = 0.f, az = 0.f, aw = 0.f;
    int cnt = 0;
    #pragma unroll
    for (int i = 0; i < TOKITER; i++) {
        int tk = tks[i];
        if (tk != 0) {
            float4 p = __ldg((const float4*)(embed + (size_t)tk * EMBED) + c);
            ax += p.x; ay += p.y; az += p.z; aw += p.w;
            cnt++;
        }
    }

    // reduce across the 8 token subgroups (same chunk c): offsets 4,8,16
    #pragma unroll
    for (int o = 4; o <= 16; o <<= 1) {
        ax += __shfl_xor_sync(0xffffffffu, ax, o);
        ay += __shfl_xor_sync(0xffffffffu, ay, o);
        az += __shfl_xor_sync(0xffffffffu, az, o);
        aw += __shfl_xor_sync(0xffffffffu, aw, o);
    }
    // count: every lane with c==0 holds a partial; zero others, full butterfly
    int cpart = (c == 0) ? cnt : 0;
    #pragma unroll
    for (int o = 16; o; o >>= 1)
        cpart += __shfl_xor_sync(0xffffffffu, cpart, o);

    float inv = __fdiv_rn(1.0f, fmaxf((float)cpart, 1.0f));

    if (g == 0) {   // lanes 0..3 hold the 16 totals (chunk c -> dims 4c..4c+3)
        savg[wib][4 * c + 0] = ax * inv;
        savg[wib][4 * c + 1] = ay * inv;
        savg[wib][4 * c + 2] = az * inv;
        savg[wib][4 * c + 3] = aw * inv;
    }
    __syncwarp();

    float avg[EMBED];
    #pragma unroll
    for (int q = 0; q < EMBED; q++) avg[q] = savg[wib][q];

    // each lane computes 2 hidden outputs
    #pragma unroll
    for (int r = 0; r < 2; r++) {
        int h = lane + 32 * r;
        const float* wrow = &sWc[h * EMBED];
        float d = 0.0f;
        #pragma unroll
        for (int q = 0; q < EMBED; q++) d = fmaf(avg[q], wrow[q], d);
        cur[(size_t)warp * HIDDEN + h] = __fadd_rn(d, sbc[h]);
    }
}

// ---------------------------------------------------------------------------
// Phase B: 10-tick stochastic spiking recurrence. One thread per neuron.
// ---------------------------------------------------------------------------
struct KeysParam { uint32_t kn0[TICKS], kn1[TICKS], kf0[TICKS], kf1[TICKS]; };

__global__ void __launch_bounds__(256)
phaseB_kernel(const float* __restrict__ cur, float* __restrict__ spk_out,
              KeysParam K, int n, int use_global_fallback) {
    int i = blockIdx.x * blockDim.x + threadIdx.x;
    if (i >= n) return;
    float* outp = use_global_fallback ? g_spk : spk_out;

    float cu = cur[i];
    float v = 0.0f, rf = 0.0f, acc = 0.0f;
    uint32_t ui = (uint32_t)i;
    const float LO = -0.99999994f;

    #pragma unroll
    for (int t = 0; t < TICKS; t++) {
        uint32_t n0, n1, f0, f1;
        tf2x32_dev(K.kn0[t], K.kn1[t], 0u, ui, n0, n1);
        tf2x32_dev(K.kf0[t], K.kf1[t], 0u, ui, f0, f1);
        uint32_t nb = n0 ^ n1;
        uint32_t fb = f0 ^ f1;

        float fr = __fsub_rn(__uint_as_float((nb >> 9) | 0x3f800000u), 1.0f);
        float u  = fmaxf(LO, __fadd_rn(__fmul_rn(fr, 2.0f), LO));
        float z  = erfinv_xla(u);
        float noise = __fmul_rn(0.01f, __fmul_rn(1.41421356237309515f, z));

        v = __fadd_rn(__fadd_rn(__fmul_rn(v, 0.98f), cu), noise);

        float uf = __fsub_rn(__uint_as_float((fb >> 9) | 0x3f800000u), 1.0f);
        bool fire = (__fsub_rn(v, rf) > 0.5f) && (uf >= 0.5f);
        float spike = fire ? 1.0f : 0.0f;
        v  = fire ? 0.0f : v;
        rf = __fadd_rn(__fmul_rn(rf, 0.95f), spike);
        acc = __fadd_rn(acc, spike);
    }
    outp[i] = __fdiv_rn(acc, 10.0f);
}

// ---------------------------------------------------------------------------
// Phase C: logits = avg_spikes @ Wr.T + br   (one warp per row)
// ---------------------------------------------------------------------------
__global__ void phaseC_kernel(const float* __restrict__ spk_in,
                              const float* __restrict__ Wr,
                              const float* __restrict__ br,
                              float* __restrict__ logits, int B,
                              int use_global_fallback) {
    const float* spk = use_global_fallback ? g_spk : spk_in;
    int gw   = (blockIdx.x * blockDim.x + threadIdx.x) >> 5;
    int lane = threadIdx.x & 31;
    if (gw >= B) return;
    float s0 = spk[gw * HIDDEN + lane];
    float s1 = spk[gw * HIDDEN + 32 + lane];
    #pragma unroll
    for (int cc = 0; cc < 4; cc++) {
        float p = __fadd_rn(__fmul_rn(s0, Wr[cc * HIDDEN + lane]),
                            __fmul_rn(s1, Wr[cc * HIDDEN + 32 + lane]));
        #pragma unroll
        for (int o = 16; o; o >>= 1)
            p = __fadd_rn(p, __shfl_xor_sync(0xffffffffu, p, o));
        if (lane == 0) logits[gw * 4 + cc] = __fadd_rn(p, br[cc]);
    }
}

// ---------------------------------------------------------------------------
extern "C" void kernel_launch(void* const* d_in, const int* in_sizes, int n_in,
                              void* d_out, int out_size) {
    const int*   tokens = (const int*)d_in[0];
    const float* embed  = (const float*)d_in[1];
    const float* Wc     = (const float*)d_in[2];
    const float* bc     = (const float*)d_in[3];
    const float* Wr     = (const float*)d_in[4];
    const float* br     = (const float*)d_in[5];

    int B = in_sizes[0] / SEQLEN;
    int n = B * HIDDEN;

    KeysParam K;
    for (int t = 0; t < TICKS; t++) {
        uint32_t kt0, kt1;
        tf2x32_host(0u, 1u, 0u, (uint32_t)t, &kt0, &kt1);
        tf2x32_host(kt0, kt1, 0u, 0u, &K.kn0[t], &K.kn1[t]);
        tf2x32_host(kt0, kt1, 0u, 1u, &K.kf0[t], &K.kf1[t]);
    }

    float* out_f = (float*)d_out;
    int need = B * 4 + B * HIDDEN;
    int fallback = (out_size < need) ? 1 : 0;
    float* spk_region = fallback ? (float*)nullptr : (out_f + B * 4);

    void* cur_ptr = nullptr;
    cudaGetSymbolAddress(&cur_ptr, g_cur);

    int blocksA = (B * 32 + 255) / 256;   // one warp per row
    phaseA_kernel<<<blocksA, 256>>>(tokens, embed, Wc, bc, (float*)cur_ptr, B);

    phaseB_kernel<<<(n + 255) / 256, 256>>>((const float*)cur_ptr,
                                            spk_region, K, n, fallback);

    phaseC_kernel<<<(B * 32 + 255) / 256, 256>>>(spk_region, Wr, br,
                                                 out_f, B, fallback);
}

// round 4
// speedup vs baseline: 1.5575x; 1.5575x over previous
#include <cuda_runtime.h>
#include <cuda_bf16.h>
#include <stdint.h>

// ============================================================================
// ChaosLanguageModel: embed-mean -> 10-tick stochastic spiking -> readout
// Replicates JAX threefry2x32 RNG bit-exactly (partitionable path).
// R4: FULLY FUSED single kernel, warp-per-row. Removes g_cur round trip,
// 2 of 3 launches, and overlaps gather-latency warps with RNG-ALU warps.
// ============================================================================

#define EMBED 16
#define HIDDEN 64
#define TICKS 10
#define SEQLEN 200
#define TOKITER (SEQLEN / 8)   // 25

// ---------------------------------------------------------------------------
// threefry2x32 (JAX rotation schedule)
// ---------------------------------------------------------------------------
__device__ __forceinline__ void tf2x32_dev(uint32_t k0, uint32_t k1,
                                           uint32_t x0, uint32_t x1,
                                           uint32_t& o0, uint32_t& o1) {
    uint32_t k2 = k0 ^ k1 ^ 0x1BD11BDAu;
#define TF_RND(r) { x0 += x1; x1 = __funnelshift_l(x1, x1, (r)); x1 ^= x0; }
    x0 += k0; x1 += k1;
    TF_RND(13) TF_RND(15) TF_RND(26) TF_RND(6)
    x0 += k1; x1 += k2 + 1u;
    TF_RND(17) TF_RND(29) TF_RND(16) TF_RND(24)
    x0 += k2; x1 += k0 + 2u;
    TF_RND(13) TF_RND(15) TF_RND(26) TF_RND(6)
    x0 += k0; x1 += k1 + 3u;
    TF_RND(17) TF_RND(29) TF_RND(16) TF_RND(24)
    x0 += k1; x1 += k2 + 4u;
    TF_RND(13) TF_RND(15) TF_RND(26) TF_RND(6)
    x0 += k2; x1 += k0 + 5u;
#undef TF_RND
    o0 = x0; o1 = x1;
}

static inline uint32_t rotl_h(uint32_t x, int r) { return (x << r) | (x >> (32 - r)); }
static void tf2x32_host(uint32_t k0, uint32_t k1, uint32_t x0, uint32_t x1,
                        uint32_t* o0, uint32_t* o1) {
    uint32_t k2 = k0 ^ k1 ^ 0x1BD11BDAu;
#define TF_RND(r) { x0 += x1; x1 = rotl_h(x1, (r)); x1 ^= x0; }
    x0 += k0; x1 += k1;
    TF_RND(13) TF_RND(15) TF_RND(26) TF_RND(6)
    x0 += k1; x1 += k2 + 1u;
    TF_RND(17) TF_RND(29) TF_RND(16) TF_RND(24)
    x0 += k2; x1 += k0 + 2u;
    TF_RND(13) TF_RND(15) TF_RND(26) TF_RND(6)
    x0 += k0; x1 += k1 + 3u;
    TF_RND(17) TF_RND(29) TF_RND(16) TF_RND(24)
    x0 += k1; x1 += k2 + 4u;
    TF_RND(13) TF_RND(15) TF_RND(26) TF_RND(6)
    x0 += k2; x1 += k0 + 5u;
#undef TF_RND
    *o0 = x0; *o1 = x1;
}

// ---------------------------------------------------------------------------
// XLA erf_inv (f32, Giles polynomial)
// ---------------------------------------------------------------------------
__device__ __forceinline__ float erfinv_xla(float x) {
    float t = __fmul_rn(x, x);
    float w = -log1pf(-t);
    float p;
    if (w < 5.0f) {
        w = __fsub_rn(w, 2.5f);
        p = 2.81022636e-08f;
        p = __fadd_rn(__fmul_rn(p, w),  3.43273939e-07f);
        p = __fadd_rn(__fmul_rn(p, w), -3.5233877e-06f);
        p = __fadd_rn(__fmul_rn(p, w), -4.39150654e-06f);
        p = __fadd_rn(__fmul_rn(p, w),  0.00021858087f);
        p = __fadd_rn(__fmul_rn(p, w), -0.00125372503f);
        p = __fadd_rn(__fmul_rn(p, w), -0.00417768164f);
        p = __fadd_rn(__fmul_rn(p, w),  0.246640727f);
        p = __fadd_rn(__fmul_rn(p, w),  1.50140941f);
    } else {
        w = __fsub_rn(__fsqrt_rn(w), 3.0f);
        p = -0.000200214257f;
        p = __fadd_rn(__fmul_rn(p, w),  0.000100950558f);
        p = __fadd_rn(__fmul_rn(p, w),  0.00134934322f);
        p = __fadd_rn(__fmul_rn(p, w), -0.00367342844f);
        p = __fadd_rn(__fmul_rn(p, w),  0.00573950773f);
        p = __fadd_rn(__fmul_rn(p, w), -0.0076224613f);
        p = __fadd_rn(__fmul_rn(p, w),  0.00943887047f);
        p = __fadd_rn(__fmul_rn(p, w),  1.00167406f);
        p = __fadd_rn(__fmul_rn(p, w),  2.83297682f);
    }
    return __fmul_rn(p, x);
}

struct KeysParam { uint32_t kn0[TICKS], kn1[TICKS], kf0[TICKS], kf1[TICKS]; };

// ---------------------------------------------------------------------------
// One neuron-pair tick chain, inlined per tick below via macro-free helper.
// (fire semantics identical to rounds 1-3)
// ---------------------------------------------------------------------------
__device__ __forceinline__ void tick_neuron(float cu, uint32_t nb, uint32_t fb,
                                            float& v, float& rf, float& acc) {
    const float LO = -0.99999994f;
    float fr = __fsub_rn(__uint_as_float((nb >> 9) | 0x3f800000u), 1.0f);
    float u  = fmaxf(LO, __fadd_rn(__fmul_rn(fr, 2.0f), LO));
    float z  = erfinv_xla(u);
    float noise = __fmul_rn(0.01f, __fmul_rn(1.41421356237309515f, z));
    v = __fadd_rn(__fadd_rn(__fmul_rn(v, 0.98f), cu), noise);
    float uf = __fsub_rn(__uint_as_float((fb >> 9) | 0x3f800000u), 1.0f);
    bool fire = (__fsub_rn(v, rf) > 0.5f) && (uf >= 0.5f);
    float spike = fire ? 1.0f : 0.0f;
    v  = fire ? 0.0f : v;
    rf = __fadd_rn(__fmul_rn(rf, 0.95f), spike);
    acc = __fadd_rn(acc, spike);
}

// ---------------------------------------------------------------------------
// FUSED kernel: warp per row.
// ---------------------------------------------------------------------------
__global__ void __launch_bounds__(256)
fused_kernel(const int* __restrict__ tokens,
             const float* __restrict__ embed,
             const float* __restrict__ Wc,
             const float* __restrict__ bc,
             const float* __restrict__ Wr,
             const float* __restrict__ br,
             float* __restrict__ logits,      // [B,4]
             float* __restrict__ spk_out,     // [B,64]
             KeysParam K, int B) {
    __shared__ float sWc[HIDDEN * EMBED];   // 4 KB
    __shared__ float sbc[HIDDEN];
    __shared__ float sWr[4 * HIDDEN];       // 1 KB
    __shared__ float sbr[4];
    __shared__ float savg[8][EMBED];        // per-warp avg broadcast

    int tid = threadIdx.x;
    for (int i = tid; i < HIDDEN * EMBED; i += 256) sWc[i] = Wc[i];
    if (tid < HIDDEN) sbc[tid] = bc[tid];
    for (int i = tid; i < 4 * HIDDEN; i += 256) sWr[i] = Wr[i];
    if (tid < 4) sbr[tid] = br[tid];
    __syncthreads();

    int warp = (blockIdx.x * 256 + tid) >> 5;
    int wib  = (tid >> 5);
    int lane = tid & 31;
    if (warp >= B) return;

    // ---------------- phase A: masked-mean embedding ----------------
    int g = lane >> 2;      // token subgroup 0..7
    int c = lane & 3;       // dim chunk 0..3
    const int* trow = tokens + (size_t)warp * SEQLEN;

    int tks[TOKITER];
    #pragma unroll
    for (int i = 0; i < TOKITER; i++)
        tks[i] = __ldg(trow + i * 8 + g);

    float ax = 0.f, ay = 0.f, az = 0.f, aw = 0.f;
    int cnt = 0;
    #pragma unroll
    for (int i = 0; i < TOKITER; i++) {
        int tk = tks[i];
        if (tk != 0) {
            float4 p = __ldg((const float4*)(embed + (size_t)tk * EMBED) + c);
            ax += p.x; ay += p.y; az += p.z; aw += p.w;
            cnt++;
        }
    }
    #pragma unroll
    for (int o = 4; o <= 16; o <<= 1) {
        ax += __shfl_xor_sync(0xffffffffu, ax, o);
        ay += __shfl_xor_sync(0xffffffffu, ay, o);
        az += __shfl_xor_sync(0xffffffffu, az, o);
        aw += __shfl_xor_sync(0xffffffffu, aw, o);
    }
    int cpart = (c == 0) ? cnt : 0;
    #pragma unroll
    for (int o = 16; o; o >>= 1)
        cpart += __shfl_xor_sync(0xffffffffu, cpart, o);

    float inv = __fdiv_rn(1.0f, fmaxf((float)cpart, 1.0f));
    if (g == 0) {
        savg[wib][4 * c + 0] = ax * inv;
        savg[wib][4 * c + 1] = ay * inv;
        savg[wib][4 * c + 2] = az * inv;
        savg[wib][4 * c + 3] = aw * inv;
    }
    __syncwarp();

    float avg[EMBED];
    #pragma unroll
    for (int q = 0; q < EMBED; q++) avg[q] = savg[wib][q];

    // cur for 2 neurons: h0 = lane, h1 = lane+32
    float cu0 = 0.0f, cu1 = 0.0f;
    {
        const float* w0 = &sWc[lane * EMBED];
        const float* w1 = &sWc[(lane + 32) * EMBED];
        #pragma unroll
        for (int q = 0; q < EMBED; q++) {
            cu0 = fmaf(avg[q], w0[q], cu0);
            cu1 = fmaf(avg[q], w1[q], cu1);
        }
        cu0 = __fadd_rn(cu0, sbc[lane]);
        cu1 = __fadd_rn(cu1, sbc[lane + 32]);
    }

    // ---------------- phase B: 10-tick recurrence, 2 neurons/lane ----------
    uint32_t i0 = (uint32_t)(warp * HIDDEN + lane);
    uint32_t i1 = i0 + 32u;
    float v0 = 0.f, rf0 = 0.f, ac0 = 0.f;
    float v1 = 0.f, rf1 = 0.f, ac1 = 0.f;

    #pragma unroll
    for (int t = 0; t < TICKS; t++) {
        uint32_t n00, n01, f00, f01, n10, n11, f10, f11;
        tf2x32_dev(K.kn0[t], K.kn1[t], 0u, i0, n00, n01);
        tf2x32_dev(K.kf0[t], K.kf1[t], 0u, i0, f00, f01);
        tf2x32_dev(K.kn0[t], K.kn1[t], 0u, i1, n10, n11);
        tf2x32_dev(K.kf0[t], K.kf1[t], 0u, i1, f10, f11);
        tick_neuron(cu0, n00 ^ n01, f00 ^ f01, v0, rf0, ac0);
        tick_neuron(cu1, n10 ^ n11, f10 ^ f11, v1, rf1, ac1);
    }

    float s0 = __fdiv_rn(ac0, 10.0f);
    float s1 = __fdiv_rn(ac1, 10.0f);

    // ---------------- phase C: readout + spike write -----------------------
    spk_out[(size_t)warp * HIDDEN + lane]      = s0;
    spk_out[(size_t)warp * HIDDEN + lane + 32] = s1;

    #pragma unroll
    for (int cc = 0; cc < 4; cc++) {
        float p = __fadd_rn(__fmul_rn(s0, sWr[cc * HIDDEN + lane]),
                            __fmul_rn(s1, sWr[cc * HIDDEN + 32 + lane]));
        #pragma unroll
        for (int o = 16; o; o >>= 1)
            p = __fadd_rn(p, __shfl_xor_sync(0xffffffffu, p, o));
        if (lane == 0) logits[(size_t)warp * 4 + cc] = __fadd_rn(p, sbr[cc]);
    }
}

// ---------------------------------------------------------------------------
extern "C" void kernel_launch(void* const* d_in, const int* in_sizes, int n_in,
                              void* d_out, int out_size) {
    const int*   tokens = (const int*)d_in[0];
    const float* embed  = (const float*)d_in[1];
    const float* Wc     = (const float*)d_in[2];
    const float* bc     = (const float*)d_in[3];
    const float* Wr     = (const float*)d_in[4];
    const float* br     = (const float*)d_in[5];

    int B = in_sizes[0] / SEQLEN;

    KeysParam K;
    for (int t = 0; t < TICKS; t++) {
        uint32_t kt0, kt1;
        tf2x32_host(0u, 1u, 0u, (uint32_t)t, &kt0, &kt1);
        tf2x32_host(kt0, kt1, 0u, 0u, &K.kn0[t], &K.kn1[t]);
        tf2x32_host(kt0, kt1, 0u, 1u, &K.kf0[t], &K.kf1[t]);
    }

    float* out_f = (float*)d_out;
    float* spk_region = out_f + (size_t)B * 4;

    int blocks = (B * 32 + 255) / 256;   // one warp per row
    fused_kernel<<<blocks, 256>>>(tokens, embed, Wc, bc, Wr, br,
                                  out_f, spk_region, K, B);
}

// round 8
// speedup vs baseline: 1.6952x; 1.0884x over previous
#include <cuda_runtime.h>
#include <cuda_bf16.h>
#include <stdint.h>

// ============================================================================
// ChaosLanguageModel: embed-mean -> 10-tick stochastic spiking -> readout
// Replicates JAX threefry2x32 RNG bit-exactly (partitionable path).
// R5: fused kernel + host-precomputed threefry key schedule (uniform-pipe
// LDCU), sign-bit fail test, 64-reg budget for 4-way threefry ILP.
// ============================================================================

#define EMBED 16
#define HIDDEN 64
#define TICKS 10
#define SEQLEN 200
#define TOKITER (SEQLEN / 8)   // 25

// ---------------------------------------------------------------------------
// threefry2x32 with precomputed per-tick schedule:
// s = { k0, k1, k2, k2+1, k0+2, k1+3, k2+4, k0+5 }
// counter is (0, i):  x0 = k0, x1 = i + k1  (first key-inject folded)
// ---------------------------------------------------------------------------
__device__ __forceinline__ void tf_pre(const uint32_t* __restrict__ s,
                                       uint32_t x1in,
                                       uint32_t& o0, uint32_t& o1) {
#define TF_RND(r) { x0 += x1; x1 = __funnelshift_l(x1, x1, (r)); x1 ^= x0; }
    uint32_t x0 = s[0];
    uint32_t x1 = x1in + s[1];
    TF_RND(13) TF_RND(15) TF_RND(26) TF_RND(6)
    x0 += s[1]; x1 += s[3];          // k1, k2+1
    TF_RND(17) TF_RND(29) TF_RND(16) TF_RND(24)
    x0 += s[2]; x1 += s[4];          // k2, k0+2
    TF_RND(13) TF_RND(15) TF_RND(26) TF_RND(6)
    x0 += s[0]; x1 += s[5];          // k0, k1+3
    TF_RND(17) TF_RND(29) TF_RND(16) TF_RND(24)
    x0 += s[1]; x1 += s[6];          // k1, k2+4
    TF_RND(13) TF_RND(15) TF_RND(26) TF_RND(6)
    x0 += s[2]; x1 += s[7];          // k2, k0+5
#undef TF_RND
    o0 = x0; o1 = x1;
}

static inline uint32_t rotl_h(uint32_t x, int r) { return (x << r) | (x >> (32 - r)); }
static void tf2x32_host(uint32_t k0, uint32_t k1, uint32_t x0, uint32_t x1,
                        uint32_t* o0, uint32_t* o1) {
    uint32_t k2 = k0 ^ k1 ^ 0x1BD11BDAu;
#define TF_RND(r) { x0 += x1; x1 = rotl_h(x1, (r)); x1 ^= x0; }
    x0 += k0; x1 += k1;
    TF_RND(13) TF_RND(15) TF_RND(26) TF_RND(6)
    x0 += k1; x1 += k2 + 1u;
    TF_RND(17) TF_RND(29) TF_RND(16) TF_RND(24)
    x0 += k2; x1 += k0 + 2u;
    TF_RND(13) TF_RND(15) TF_RND(26) TF_RND(6)
    x0 += k0; x1 += k1 + 3u;
    TF_RND(17) TF_RND(29) TF_RND(16) TF_RND(24)
    x0 += k1; x1 += k2 + 4u;
    TF_RND(13) TF_RND(15) TF_RND(26) TF_RND(6)
    x0 += k2; x1 += k0 + 5u;
#undef TF_RND
    *o0 = x0; *o1 = x1;
}

// ---------------------------------------------------------------------------
// XLA erf_inv (f32, Giles polynomial)
// ---------------------------------------------------------------------------
__device__ __forceinline__ float erfinv_xla(float x) {
    float t = __fmul_rn(x, x);
    float w = -log1pf(-t);
    float p;
    if (w < 5.0f) {
        w = __fsub_rn(w, 2.5f);
        p = 2.81022636e-08f;
        p = __fadd_rn(__fmul_rn(p, w),  3.43273939e-07f);
        p = __fadd_rn(__fmul_rn(p, w), -3.5233877e-06f);
        p = __fadd_rn(__fmul_rn(p, w), -4.39150654e-06f);
        p = __fadd_rn(__fmul_rn(p, w),  0.00021858087f);
        p = __fadd_rn(__fmul_rn(p, w), -0.00125372503f);
        p = __fadd_rn(__fmul_rn(p, w), -0.00417768164f);
        p = __fadd_rn(__fmul_rn(p, w),  0.246640727f);
        p = __fadd_rn(__fmul_rn(p, w),  1.50140941f);
    } else {
        w = __fsub_rn(__fsqrt_rn(w), 3.0f);
        p = -0.000200214257f;
        p = __fadd_rn(__fmul_rn(p, w),  0.000100950558f);
        p = __fadd_rn(__fmul_rn(p, w),  0.00134934322f);
        p = __fadd_rn(__fmul_rn(p, w), -0.00367342844f);
        p = __fadd_rn(__fmul_rn(p, w),  0.00573950773f);
        p = __fadd_rn(__fmul_rn(p, w), -0.0076224613f);
        p = __fadd_rn(__fmul_rn(p, w),  0.00943887047f);
        p = __fadd_rn(__fmul_rn(p, w),  1.00167406f);
        p = __fadd_rn(__fmul_rn(p, w),  2.83297682f);
    }
    return __fmul_rn(p, x);
}

struct KeysParam { uint32_t nk[TICKS][8]; uint32_t fk[TICKS][8]; };

// ---------------------------------------------------------------------------
// One neuron tick. fail test: uniform >= 0.5  <=>  bit31(fb) set (bit-exact).
// ---------------------------------------------------------------------------
__device__ __forceinline__ void tick_neuron(float cu, uint32_t nb, uint32_t fb,
                                            float& v, float& rf, float& acc) {
    const float LO = -0.99999994f;
    float fr = __fsub_rn(__uint_as_float((nb >> 9) | 0x3f800000u), 1.0f);
    float u  = fmaxf(LO, __fadd_rn(__fmul_rn(fr, 2.0f), LO));
    float z  = erfinv_xla(u);
    float noise = __fmul_rn(0.01f, __fmul_rn(1.41421356237309515f, z));
    v = __fadd_rn(__fadd_rn(__fmul_rn(v, 0.98f), cu), noise);
    bool fire = (__fsub_rn(v, rf) > 0.5f) && ((fb & 0x80000000u) != 0u);
    float spike = fire ? 1.0f : 0.0f;
    v  = fire ? 0.0f : v;
    rf = __fadd_rn(__fmul_rn(rf, 0.95f), spike);
    acc = __fadd_rn(acc, spike);
}

// ---------------------------------------------------------------------------
// FUSED kernel: warp per row, 2 neurons per lane.
// ---------------------------------------------------------------------------
__global__ void __launch_bounds__(256, 4)
fused_kernel(const int* __restrict__ tokens,
             const float* __restrict__ embed,
             const float* __restrict__ Wc,
             const float* __restrict__ bc,
             const float* __restrict__ Wr,
             const float* __restrict__ br,
             float* __restrict__ logits,      // [B,4]
             float* __restrict__ spk_out,     // [B,64]
             KeysParam K, int B) {
    __shared__ float sWc[HIDDEN * EMBED];   // 4 KB
    __shared__ float sbc[HIDDEN];
    __shared__ float sWr[4 * HIDDEN];       // 1 KB
    __shared__ float sbr[4];
    __shared__ float savg[8][EMBED];        // per-warp avg broadcast

    int tid = threadIdx.x;
    for (int i = tid; i < HIDDEN * EMBED; i += 256) sWc[i] = Wc[i];
    if (tid < HIDDEN) sbc[tid] = bc[tid];
    for (int i = tid; i < 4 * HIDDEN; i += 256) sWr[i] = Wr[i];
    if (tid < 4) sbr[tid] = br[tid];
    __syncthreads();

    int warp = (blockIdx.x * 256 + tid) >> 5;
    int wib  = (tid >> 5);
    int lane = tid & 31;
    if (warp >= B) return;

    // ---------------- phase A: masked-mean embedding ----------------
    int g = lane >> 2;      // token subgroup 0..7
    int c = lane & 3;       // dim chunk 0..3
    const int* trow = tokens + (size_t)warp * SEQLEN;

    int tks[TOKITER];
    #pragma unroll
    for (int i = 0; i < TOKITER; i++)
        tks[i] = __ldg(trow + i * 8 + g);

    float ax = 0.f, ay = 0.f, az = 0.f, aw = 0.f;
    int cnt = 0;
    #pragma unroll
    for (int i = 0; i < TOKITER; i++) {
        int tk = tks[i];
        if (tk != 0) {
            float4 p = __ldg((const float4*)(embed + (size_t)tk * EMBED) + c);
            ax += p.x; ay += p.y; az += p.z; aw += p.w;
            cnt++;
        }
    }
    #pragma unroll
    for (int o = 4; o <= 16; o <<= 1) {
        ax += __shfl_xor_sync(0xffffffffu, ax, o);
        ay += __shfl_xor_sync(0xffffffffu, ay, o);
        az += __shfl_xor_sync(0xffffffffu, az, o);
        aw += __shfl_xor_sync(0xffffffffu, aw, o);
    }
    int cpart = (c == 0) ? cnt : 0;
    #pragma unroll
    for (int o = 16; o; o >>= 1)
        cpart += __shfl_xor_sync(0xffffffffu, cpart, o);

    float inv = __fdiv_rn(1.0f, fmaxf((float)cpart, 1.0f));
    if (g == 0) {
        savg[wib][4 * c + 0] = ax * inv;
        savg[wib][4 * c + 1] = ay * inv;
        savg[wib][4 * c + 2] = az * inv;
        savg[wib][4 * c + 3] = aw * inv;
    }
    __syncwarp();

    float avg[EMBED];
    #pragma unroll
    for (int q = 0; q < EMBED; q++) avg[q] = savg[wib][q];

    // cur for 2 neurons: h0 = lane, h1 = lane+32
    float cu0 = 0.0f, cu1 = 0.0f;
    {
        const float* w0 = &sWc[lane * EMBED];
        const float* w1 = &sWc[(lane + 32) * EMBED];
        #pragma unroll
        for (int q = 0; q < EMBED; q++) {
            cu0 = fmaf(avg[q], w0[q], cu0);
            cu1 = fmaf(avg[q], w1[q], cu1);
        }
        cu0 = __fadd_rn(cu0, sbc[lane]);
        cu1 = __fadd_rn(cu1, sbc[lane + 32]);
    }

    // ---------------- phase B: 10-tick recurrence, 2 neurons/lane ----------
    uint32_t i0 = (uint32_t)(warp * HIDDEN + lane);
    uint32_t i1 = i0 + 32u;
    float v0 = 0.f, rf0 = 0.f, ac0 = 0.f;
    float v1 = 0.f, rf1 = 0.f, ac1 = 0.f;

    #pragma unroll
    for (int t = 0; t < TICKS; t++) {
        uint32_t a0, a1, b0, b1, c0, c1, d0, d1;
        tf_pre(K.nk[t], i0, a0, a1);     // noise, neuron 0
        tf_pre(K.fk[t], i0, b0, b1);     // fail,  neuron 0
        tf_pre(K.nk[t], i1, c0, c1);     // noise, neuron 1
        tf_pre(K.fk[t], i1, d0, d1);     // fail,  neuron 1
        tick_neuron(cu0, a0 ^ a1, b0 ^ b1, v0, rf0, ac0);
        tick_neuron(cu1, c0 ^ c1, d0 ^ d1, v1, rf1, ac1);
    }

    float s0 = __fdiv_rn(ac0, 10.0f);
    float s1 = __fdiv_rn(ac1, 10.0f);

    // ---------------- phase C: readout + spike write -----------------------
    spk_out[(size_t)warp * HIDDEN + lane]      = s0;
    spk_out[(size_t)warp * HIDDEN + lane + 32] = s1;

    #pragma unroll
    for (int cc = 0; cc < 4; cc++) {
        float p = __fadd_rn(__fmul_rn(s0, sWr[cc * HIDDEN + lane]),
                            __fmul_rn(s1, sWr[cc * HIDDEN + 32 + lane]));
        #pragma unroll
        for (int o = 16; o; o >>= 1)
            p = __fadd_rn(p, __shfl_xor_sync(0xffffffffu, p, o));
        if (lane == 0) logits[(size_t)warp * 4 + cc] = __fadd_rn(p, sbr[cc]);
    }
}

// ---------------------------------------------------------------------------
extern "C" void kernel_launch(void* const* d_in, const int* in_sizes, int n_in,
                              void* d_out, int out_size) {
    const int*   tokens = (const int*)d_in[0];
    const float* embed  = (const float*)d_in[1];
    const float* Wc     = (const float*)d_in[2];
    const float* bc     = (const float*)d_in[3];
    const float* Wr     = (const float*)d_in[4];
    const float* br     = (const float*)d_in[5];

    int B = in_sizes[0] / SEQLEN;

    // per-tick keys (JAX partitionable path), expanded key schedule
    KeysParam K;
    for (int t = 0; t < TICKS; t++) {
        uint32_t kt0, kt1, n0, n1, f0, f1;
        tf2x32_host(0u, 1u, 0u, (uint32_t)t, &kt0, &kt1);
        tf2x32_host(kt0, kt1, 0u, 0u, &n0, &n1);
        tf2x32_host(kt0, kt1, 0u, 1u, &f0, &f1);
        uint32_t n2 = n0 ^ n1 ^ 0x1BD11BDAu;
        uint32_t f2 = f0 ^ f1 ^ 0x1BD11BDAu;
        uint32_t ns[8] = { n0, n1, n2, n2 + 1u, n0 + 2u, n1 + 3u, n2 + 4u, n0 + 5u };
        uint32_t fs[8] = { f0, f1, f2, f2 + 1u, f0 + 2u, f1 + 3u, f2 + 4u, f0 + 5u };
        for (int j = 0; j < 8; j++) { K.nk[t][j] = ns[j]; K.fk[t][j] = fs[j]; }
    }

    float* out_f = (float*)d_out;
    float* spk_region = out_f + (size_t)B * 4;

    int blocks = (B * 32 + 255) / 256;   // one warp per row
    fused_kernel<<<blocks, 256>>>(tokens, embed, Wc, bc, Wr, br,
                                  out_f, spk_region, K, B);
}

// round 9
// speedup vs baseline: 1.7111x; 1.0094x over previous
#include <cuda_runtime.h>
#include <cuda_bf16.h>
#include <stdint.h>

// ============================================================================
// ChaosLanguageModel: embed-mean -> 10-tick stochastic spiking -> readout
// Replicates JAX threefry2x32 RNG bit-exactly (partitionable path).
// R6: tf4 = 4 threefry streams interleaved round-by-round (forces ILP so the
// lat-4 round chains overlap); fmaxf clamp removed (arithmetic no-op).
// ============================================================================

#define EMBED 16
#define HIDDEN 64
#define TICKS 10
#define SEQLEN 200
#define TOKITER (SEQLEN / 8)   // 25

// ---------------------------------------------------------------------------
// 4-stream threefry2x32 with precomputed per-tick schedules.
// ns/fs = { k0, k1, k2, k2+1, k0+2, k1+3, k2+4, k0+5 }
// streams: (ns,i0) (fs,i0) (ns,i1) (fs,i1); counter (0,i) folds first inject.
// ---------------------------------------------------------------------------
__device__ __forceinline__ void tf4(const uint32_t* __restrict__ ns,
                                    const uint32_t* __restrict__ fs,
                                    uint32_t i0, uint32_t i1,
                                    uint32_t& nb0, uint32_t& fb0,
                                    uint32_t& nb1, uint32_t& fb1) {
    uint32_t a0 = ns[0], a1 = i0 + ns[1];
    uint32_t b0 = fs[0], b1 = i0 + fs[1];
    uint32_t c0 = ns[0], c1 = i1 + ns[1];
    uint32_t d0 = fs[0], d1 = i1 + fs[1];
#define R4(r) { a0 += a1; b0 += b1; c0 += c1; d0 += d1;                   \
                a1 = __funnelshift_l(a1, a1, (r));                        \
                b1 = __funnelshift_l(b1, b1, (r));                        \
                c1 = __funnelshift_l(c1, c1, (r));                        \
                d1 = __funnelshift_l(d1, d1, (r));                        \
                a1 ^= a0; b1 ^= b0; c1 ^= c0; d1 ^= d0; }
#define INJ4(j0, j1) { a0 += ns[j0]; a1 += ns[j1];                        \
                       b0 += fs[j0]; b1 += fs[j1];                        \
                       c0 += ns[j0]; c1 += ns[j1];                        \
                       d0 += fs[j0]; d1 += fs[j1]; }
    R4(13) R4(15) R4(26) R4(6)
    INJ4(1, 3)
    R4(17) R4(29) R4(16) R4(24)
    INJ4(2, 4)
    R4(13) R4(15) R4(26) R4(6)
    INJ4(0, 5)
    R4(17) R4(29) R4(16) R4(24)
    INJ4(1, 6)
    R4(13) R4(15) R4(26) R4(6)
    INJ4(2, 7)
#undef R4
#undef INJ4
    nb0 = a0 ^ a1; fb0 = b0 ^ b1;
    nb1 = c0 ^ c1; fb1 = d0 ^ d1;
}

static inline uint32_t rotl_h(uint32_t x, int r) { return (x << r) | (x >> (32 - r)); }
static void tf2x32_host(uint32_t k0, uint32_t k1, uint32_t x0, uint32_t x1,
                        uint32_t* o0, uint32_t* o1) {
    uint32_t k2 = k0 ^ k1 ^ 0x1BD11BDAu;
#define TF_RND(r) { x0 += x1; x1 = rotl_h(x1, (r)); x1 ^= x0; }
    x0 += k0; x1 += k1;
    TF_RND(13) TF_RND(15) TF_RND(26) TF_RND(6)
    x0 += k1; x1 += k2 + 1u;
    TF_RND(17) TF_RND(29) TF_RND(16) TF_RND(24)
    x0 += k2; x1 += k0 + 2u;
    TF_RND(13) TF_RND(15) TF_RND(26) TF_RND(6)
    x0 += k0; x1 += k1 + 3u;
    TF_RND(17) TF_RND(29) TF_RND(16) TF_RND(24)
    x0 += k1; x1 += k2 + 4u;
    TF_RND(13) TF_RND(15) TF_RND(26) TF_RND(6)
    x0 += k2; x1 += k0 + 5u;
#undef TF_RND
    *o0 = x0; *o1 = x1;
}

// ---------------------------------------------------------------------------
// XLA erf_inv (f32, Giles polynomial)
// ---------------------------------------------------------------------------
__device__ __forceinline__ float erfinv_xla(float x) {
    float t = __fmul_rn(x, x);
    float w = -log1pf(-t);
    float p;
    if (w < 5.0f) {
        w = __fsub_rn(w, 2.5f);
        p = 2.81022636e-08f;
        p = __fadd_rn(__fmul_rn(p, w),  3.43273939e-07f);
        p = __fadd_rn(__fmul_rn(p, w), -3.5233877e-06f);
        p = __fadd_rn(__fmul_rn(p, w), -4.39150654e-06f);
        p = __fadd_rn(__fmul_rn(p, w),  0.00021858087f);
        p = __fadd_rn(__fmul_rn(p, w), -0.00125372503f);
        p = __fadd_rn(__fmul_rn(p, w), -0.00417768164f);
        p = __fadd_rn(__fmul_rn(p, w),  0.246640727f);
        p = __fadd_rn(__fmul_rn(p, w),  1.50140941f);
    } else {
        w = __fsub_rn(__fsqrt_rn(w), 3.0f);
        p = -0.000200214257f;
        p = __fadd_rn(__fmul_rn(p, w),  0.000100950558f);
        p = __fadd_rn(__fmul_rn(p, w),  0.00134934322f);
        p = __fadd_rn(__fmul_rn(p, w), -0.00367342844f);
        p = __fadd_rn(__fmul_rn(p, w),  0.00573950773f);
        p = __fadd_rn(__fmul_rn(p, w), -0.0076224613f);
        p = __fadd_rn(__fmul_rn(p, w),  0.00943887047f);
        p = __fadd_rn(__fmul_rn(p, w),  1.00167406f);
        p = __fadd_rn(__fmul_rn(p, w),  2.83297682f);
    }
    return __fmul_rn(p, x);
}

struct KeysParam { uint32_t nk[TICKS][8]; uint32_t fk[TICKS][8]; };

// ---------------------------------------------------------------------------
// One neuron tick. fail test via sign bit; clamp removed (no-op for fr>=0).
// ---------------------------------------------------------------------------
__device__ __forceinline__ void tick_neuron(float cu, uint32_t nb, uint32_t fb,
                                            float& v, float& rf, float& acc) {
    const float LO = -0.99999994f;
    float fr = __fsub_rn(__uint_as_float((nb >> 9) | 0x3f800000u), 1.0f);
    float u  = __fadd_rn(__fmul_rn(fr, 2.0f), LO);   // >= LO always
    float z  = erfinv_xla(u);
    float noise = __fmul_rn(0.01f, __fmul_rn(1.41421356237309515f, z));
    v = __fadd_rn(__fadd_rn(__fmul_rn(v, 0.98f), cu), noise);
    bool fire = (__fsub_rn(v, rf) > 0.5f) && ((fb & 0x80000000u) != 0u);
    float spike = fire ? 1.0f : 0.0f;
    v  = fire ? 0.0f : v;
    rf = __fadd_rn(__fmul_rn(rf, 0.95f), spike);
    acc = __fadd_rn(acc, spike);
}

// ---------------------------------------------------------------------------
// FUSED kernel: warp per row, 2 neurons per lane.
// ---------------------------------------------------------------------------
__global__ void __launch_bounds__(256, 4)
fused_kernel(const int* __restrict__ tokens,
             const float* __restrict__ embed,
             const float* __restrict__ Wc,
             const float* __restrict__ bc,
             const float* __restrict__ Wr,
             const float* __restrict__ br,
             float* __restrict__ logits,      // [B,4]
             float* __restrict__ spk_out,     // [B,64]
             KeysParam K, int B) {
    __shared__ float sWc[HIDDEN * EMBED];   // 4 KB
    __shared__ float sbc[HIDDEN];
    __shared__ float sWr[4 * HIDDEN];       // 1 KB
    __shared__ float sbr[4];
    __shared__ float savg[8][EMBED];        // per-warp avg broadcast

    int tid = threadIdx.x;
    for (int i = tid; i < HIDDEN * EMBED; i += 256) sWc[i] = Wc[i];
    if (tid < HIDDEN) sbc[tid] = bc[tid];
    for (int i = tid; i < 4 * HIDDEN; i += 256) sWr[i] = Wr[i];
    if (tid < 4) sbr[tid] = br[tid];
    __syncthreads();

    int warp = (blockIdx.x * 256 + tid) >> 5;
    int wib  = (tid >> 5);
    int lane = tid & 31;
    if (warp >= B) return;

    // ---------------- phase A: masked-mean embedding ----------------
    int g = lane >> 2;      // token subgroup 0..7
    int c = lane & 3;       // dim chunk 0..3
    const int* trow = tokens + (size_t)warp * SEQLEN;

    int tks[TOKITER];
    #pragma unroll
    for (int i = 0; i < TOKITER; i++)
        tks[i] = __ldg(trow + i * 8 + g);

    float ax = 0.f, ay = 0.f, az = 0.f, aw = 0.f;
    int cnt = 0;
    #pragma unroll
    for (int i = 0; i < TOKITER; i++) {
        int tk = tks[i];
        if (tk != 0) {
            float4 p = __ldg((const float4*)(embed + (size_t)tk * EMBED) + c);
            ax += p.x; ay += p.y; az += p.z; aw += p.w;
            cnt++;
        }
    }
    #pragma unroll
    for (int o = 4; o <= 16; o <<= 1) {
        ax += __shfl_xor_sync(0xffffffffu, ax, o);
        ay += __shfl_xor_sync(0xffffffffu, ay, o);
        az += __shfl_xor_sync(0xffffffffu, az, o);
        aw += __shfl_xor_sync(0xffffffffu, aw, o);
    }
    int cpart = (c == 0) ? cnt : 0;
    #pragma unroll
    for (int o = 16; o; o >>= 1)
        cpart += __shfl_xor_sync(0xffffffffu, cpart, o);

    float inv = __fdiv_rn(1.0f, fmaxf((float)cpart, 1.0f));
    if (g == 0) {
        savg[wib][4 * c + 0] = ax * inv;
        savg[wib][4 * c + 1] = ay * inv;
        savg[wib][4 * c + 2] = az * inv;
        savg[wib][4 * c + 3] = aw * inv;
    }
    __syncwarp();

    float avg[EMBED];
    #pragma unroll
    for (int q = 0; q < EMBED; q++) avg[q] = savg[wib][q];

    // cur for 2 neurons: h0 = lane, h1 = lane+32
    float cu0 = 0.0f, cu1 = 0.0f;
    {
        const float* w0 = &sWc[lane * EMBED];
        const float* w1 = &sWc[(lane + 32) * EMBED];
        #pragma unroll
        for (int q = 0; q < EMBED; q++) {
            cu0 = fmaf(avg[q], w0[q], cu0);
            cu1 = fmaf(avg[q], w1[q], cu1);
        }
        cu0 = __fadd_rn(cu0, sbc[lane]);
        cu1 = __fadd_rn(cu1, sbc[lane + 32]);
    }

    // ---------------- phase B: 10-tick recurrence, 2 neurons/lane ----------
    uint32_t i0 = (uint32_t)(warp * HIDDEN + lane);
    uint32_t i1 = i0 + 32u;
    float v0 = 0.f, rf0 = 0.f, ac0 = 0.f;
    float v1 = 0.f, rf1 = 0.f, ac1 = 0.f;

    #pragma unroll
    for (int t = 0; t < TICKS; t++) {
        uint32_t nb0, fb0, nb1, fb1;
        tf4(K.nk[t], K.fk[t], i0, i1, nb0, fb0, nb1, fb1);
        tick_neuron(cu0, nb0, fb0, v0, rf0, ac0);
        tick_neuron(cu1, nb1, fb1, v1, rf1, ac1);
    }

    float s0 = __fdiv_rn(ac0, 10.0f);
    float s1 = __fdiv_rn(ac1, 10.0f);

    // ---------------- phase C: readout + spike write -----------------------
    spk_out[(size_t)warp * HIDDEN + lane]      = s0;
    spk_out[(size_t)warp * HIDDEN + lane + 32] = s1;

    #pragma unroll
    for (int cc = 0; cc < 4; cc++) {
        float p = __fadd_rn(__fmul_rn(s0, sWr[cc * HIDDEN + lane]),
                            __fmul_rn(s1, sWr[cc * HIDDEN + 32 + lane]));
        #pragma unroll
        for (int o = 16; o; o >>= 1)
            p = __fadd_rn(p, __shfl_xor_sync(0xffffffffu, p, o));
        if (lane == 0) logits[(size_t)warp * 4 + cc] = __fadd_rn(p, sbr[cc]);
    }
}

// ---------------------------------------------------------------------------
extern "C" void kernel_launch(void* const* d_in, const int* in_sizes, int n_in,
                              void* d_out, int out_size) {
    const int*   tokens = (const int*)d_in[0];
    const float* embed  = (const float*)d_in[1];
    const float* Wc     = (const float*)d_in[2];
    const float* bc     = (const float*)d_in[3];
    const float* Wr     = (const float*)d_in[4];
    const float* br     = (const float*)d_in[5];

    int B = in_sizes[0] / SEQLEN;

    // per-tick keys (JAX partitionable path), expanded key schedule
    KeysParam K;
    for (int t = 0; t < TICKS; t++) {
        uint32_t kt0, kt1, n0, n1, f0, f1;
        tf2x32_host(0u, 1u, 0u, (uint32_t)t, &kt0, &kt1);
        tf2x32_host(kt0, kt1, 0u, 0u, &n0, &n1);
        tf2x32_host(kt0, kt1, 0u, 1u, &f0, &f1);
        uint32_t n2 = n0 ^ n1 ^ 0x1BD11BDAu;
        uint32_t f2 = f0 ^ f1 ^ 0x1BD11BDAu;
        uint32_t ns[8] = { n0, n1, n2, n2 + 1u, n0 + 2u, n1 + 3u, n2 + 4u, n0 + 5u };
        uint32_t fs[8] = { f0, f1, f2, f2 + 1u, f0 + 2u, f1 + 3u, f2 + 4u, f0 + 5u };
        for (int j = 0; j < 8; j++) { K.nk[t][j] = ns[j]; K.fk[t][j] = fs[j]; }
    }

    float* out_f = (float*)d_out;
    float* spk_region = out_f + (size_t)B * 4;

    int blocks = (B * 32 + 255) / 256;   // one warp per row
    fused_kernel<<<blocks, 256>>>(tokens, embed, Wc, bc, Wr, br,
                                  out_f, spk_region, K, B);
}

// round 10
// speedup vs baseline: 1.7139x; 1.0016x over previous
#include <cuda_runtime.h>
#include <cuda_bf16.h>
#include <stdint.h>

// ============================================================================
// ChaosLanguageModel: embed-mean -> 10-tick stochastic spiking -> readout
// Replicates JAX threefry2x32 RNG bit-exactly (partitionable path).
// R7: branchless erfinv (both poly chains + FSEL). Removes 20 BSSY/BSYNC
// pairs per thread that fragmented phase B into tiny scheduling regions and
// kept the alu (threefry) and fma (erfinv) phases from interleaving.
// ============================================================================

#define EMBED 16
#define HIDDEN 64
#define TICKS 10
#define SEQLEN 200
#define TOKITER (SEQLEN / 8)   // 25

// ---------------------------------------------------------------------------
// 4-stream threefry2x32 with precomputed per-tick schedules.
// ns/fs = { k0, k1, k2, k2+1, k0+2, k1+3, k2+4, k0+5 }
// ---------------------------------------------------------------------------
__device__ __forceinline__ void tf4(const uint32_t* __restrict__ ns,
                                    const uint32_t* __restrict__ fs,
                                    uint32_t i0, uint32_t i1,
                                    uint32_t& nb0, uint32_t& fb0,
                                    uint32_t& nb1, uint32_t& fb1) {
    uint32_t a0 = ns[0], a1 = i0 + ns[1];
    uint32_t b0 = fs[0], b1 = i0 + fs[1];
    uint32_t c0 = ns[0], c1 = i1 + ns[1];
    uint32_t d0 = fs[0], d1 = i1 + fs[1];
#define R4(r) { a0 += a1; b0 += b1; c0 += c1; d0 += d1;                   \
                a1 = __funnelshift_l(a1, a1, (r));                        \
                b1 = __funnelshift_l(b1, b1, (r));                        \
                c1 = __funnelshift_l(c1, c1, (r));                        \
                d1 = __funnelshift_l(d1, d1, (r));                        \
                a1 ^= a0; b1 ^= b0; c1 ^= c0; d1 ^= d0; }
#define INJ4(j0, j1) { a0 += ns[j0]; a1 += ns[j1];                        \
                       b0 += fs[j0]; b1 += fs[j1];                        \
                       c0 += ns[j0]; c1 += ns[j1];                        \
                       d0 += fs[j0]; d1 += fs[j1]; }
    R4(13) R4(15) R4(26) R4(6)
    INJ4(1, 3)
    R4(17) R4(29) R4(16) R4(24)
    INJ4(2, 4)
    R4(13) R4(15) R4(26) R4(6)
    INJ4(0, 5)
    R4(17) R4(29) R4(16) R4(24)
    INJ4(1, 6)
    R4(13) R4(15) R4(26) R4(6)
    INJ4(2, 7)
#undef R4
#undef INJ4
    nb0 = a0 ^ a1; fb0 = b0 ^ b1;
    nb1 = c0 ^ c1; fb1 = d0 ^ d1;
}

static inline uint32_t rotl_h(uint32_t x, int r) { return (x << r) | (x >> (32 - r)); }
static void tf2x32_host(uint32_t k0, uint32_t k1, uint32_t x0, uint32_t x1,
                        uint32_t* o0, uint32_t* o1) {
    uint32_t k2 = k0 ^ k1 ^ 0x1BD11BDAu;
#define TF_RND(r) { x0 += x1; x1 = rotl_h(x1, (r)); x1 ^= x0; }
    x0 += k0; x1 += k1;
    TF_RND(13) TF_RND(15) TF_RND(26) TF_RND(6)
    x0 += k1; x1 += k2 + 1u;
    TF_RND(17) TF_RND(29) TF_RND(16) TF_RND(24)
    x0 += k2; x1 += k0 + 2u;
    TF_RND(13) TF_RND(15) TF_RND(26) TF_RND(6)
    x0 += k0; x1 += k1 + 3u;
    TF_RND(17) TF_RND(29) TF_RND(16) TF_RND(24)
    x0 += k1; x1 += k2 + 4u;
    TF_RND(13) TF_RND(15) TF_RND(26) TF_RND(6)
    x0 += k2; x1 += k0 + 5u;
#undef TF_RND
    *o0 = x0; *o1 = x1;
}

// ---------------------------------------------------------------------------
// XLA erf_inv (f32, Giles) — BRANCHLESS: both chains evaluated, FSEL select.
// Each chain's float ops are identical to the branchy version -> bit-exact.
// ---------------------------------------------------------------------------
__device__ __forceinline__ float erfinv_xla(float x) {
    float t = __fmul_rn(x, x);
    float w = -log1pf(-t);

    // central chain (w < 5)
    float wa = __fsub_rn(w, 2.5f);
    float pa = 2.81022636e-08f;
    pa = __fadd_rn(__fmul_rn(pa, wa),  3.43273939e-07f);
    pa = __fadd_rn(__fmul_rn(pa, wa), -3.5233877e-06f);
    pa = __fadd_rn(__fmul_rn(pa, wa), -4.39150654e-06f);
    pa = __fadd_rn(__fmul_rn(pa, wa),  0.00021858087f);
    pa = __fadd_rn(__fmul_rn(pa, wa), -0.00125372503f);
    pa = __fadd_rn(__fmul_rn(pa, wa), -0.00417768164f);
    pa = __fadd_rn(__fmul_rn(pa, wa),  0.246640727f);
    pa = __fadd_rn(__fmul_rn(pa, wa),  1.50140941f);

    // tail chain (w >= 5)
    float wb = __fsub_rn(__fsqrt_rn(w), 3.0f);
    float pb = -0.000200214257f;
    pb = __fadd_rn(__fmul_rn(pb, wb),  0.000100950558f);
    pb = __fadd_rn(__fmul_rn(pb, wb),  0.00134934322f);
    pb = __fadd_rn(__fmul_rn(pb, wb), -0.00367342844f);
    pb = __fadd_rn(__fmul_rn(pb, wb),  0.00573950773f);
    pb = __fadd_rn(__fmul_rn(pb, wb), -0.0076224613f);
    pb = __fadd_rn(__fmul_rn(pb, wb),  0.00943887047f);
    pb = __fadd_rn(__fmul_rn(pb, wb),  1.00167406f);
    pb = __fadd_rn(__fmul_rn(pb, wb),  2.83297682f);

    float p = (w < 5.0f) ? pa : pb;
    return __fmul_rn(p, x);
}

struct KeysParam { uint32_t nk[TICKS][8]; uint32_t fk[TICKS][8]; };

// ---------------------------------------------------------------------------
// One neuron tick. fail test via sign bit; clamp removed (no-op for fr>=0).
// ---------------------------------------------------------------------------
__device__ __forceinline__ void tick_neuron(float cu, uint32_t nb, uint32_t fb,
                                            float& v, float& rf, float& acc) {
    const float LO = -0.99999994f;
    float fr = __fsub_rn(__uint_as_float((nb >> 9) | 0x3f800000u), 1.0f);
    float u  = __fadd_rn(__fmul_rn(fr, 2.0f), LO);   // >= LO always
    float z  = erfinv_xla(u);
    float noise = __fmul_rn(0.01f, __fmul_rn(1.41421356237309515f, z));
    v = __fadd_rn(__fadd_rn(__fmul_rn(v, 0.98f), cu), noise);
    bool fire = (__fsub_rn(v, rf) > 0.5f) && ((fb & 0x80000000u) != 0u);
    float spike = fire ? 1.0f : 0.0f;
    v  = fire ? 0.0f : v;
    rf = __fadd_rn(__fmul_rn(rf, 0.95f), spike);
    acc = __fadd_rn(acc, spike);
}

// ---------------------------------------------------------------------------
// FUSED kernel: warp per row, 2 neurons per lane.
// ---------------------------------------------------------------------------
__global__ void __launch_bounds__(256, 4)
fused_kernel(const int* __restrict__ tokens,
             const float* __restrict__ embed,
             const float* __restrict__ Wc,
             const float* __restrict__ bc,
             const float* __restrict__ Wr,
             const float* __restrict__ br,
             float* __restrict__ logits,      // [B,4]
             float* __restrict__ spk_out,     // [B,64]
             KeysParam K, int B) {
    __shared__ float sWc[HIDDEN * EMBED];   // 4 KB
    __shared__ float sbc[HIDDEN];
    __shared__ float sWr[4 * HIDDEN];       // 1 KB
    __shared__ float sbr[4];
    __shared__ float savg[8][EMBED];        // per-warp avg broadcast

    int tid = threadIdx.x;
    for (int i = tid; i < HIDDEN * EMBED; i += 256) sWc[i] = Wc[i];
    if (tid < HIDDEN) sbc[tid] = bc[tid];
    for (int i = tid; i < 4 * HIDDEN; i += 256) sWr[i] = Wr[i];
    if (tid < 4) sbr[tid] = br[tid];
    __syncthreads();

    int warp = (blockIdx.x * 256 + tid) >> 5;
    int wib  = (tid >> 5);
    int lane = tid & 31;
    if (warp >= B) return;

    // ---------------- phase A: masked-mean embedding ----------------
    int g = lane >> 2;      // token subgroup 0..7
    int c = lane & 3;       // dim chunk 0..3
    const int* trow = tokens + (size_t)warp * SEQLEN;

    int tks[TOKITER];
    #pragma unroll
    for (int i = 0; i < TOKITER; i++)
        tks[i] = __ldg(trow + i * 8 + g);

    float ax = 0.f, ay = 0.f, az = 0.f, aw = 0.f;
    int cnt = 0;
    #pragma unroll
    for (int i = 0; i < TOKITER; i++) {
        int tk = tks[i];
        if (tk != 0) {
            float4 p = __ldg((const float4*)(embed + (size_t)tk * EMBED) + c);
            ax += p.x; ay += p.y; az += p.z; aw += p.w;
            cnt++;
        }
    }
    #pragma unroll
    for (int o = 4; o <= 16; o <<= 1) {
        ax += __shfl_xor_sync(0xffffffffu, ax, o);
        ay += __shfl_xor_sync(0xffffffffu, ay, o);
        az += __shfl_xor_sync(0xffffffffu, az, o);
        aw += __shfl_xor_sync(0xffffffffu, aw, o);
    }
    int cpart = (c == 0) ? cnt : 0;
    #pragma unroll
    for (int o = 16; o; o >>= 1)
        cpart += __shfl_xor_sync(0xffffffffu, cpart, o);

    float inv = __fdiv_rn(1.0f, fmaxf((float)cpart, 1.0f));
    if (g == 0) {
        savg[wib][4 * c + 0] = ax * inv;
        savg[wib][4 * c + 1] = ay * inv;
        savg[wib][4 * c + 2] = az * inv;
        savg[wib][4 * c + 3] = aw * inv;
    }
    __syncwarp();

    float avg[EMBED];
    #pragma unroll
    for (int q = 0; q < EMBED; q++) avg[q] = savg[wib][q];

    // cur for 2 neurons: h0 = lane, h1 = lane+32
    float cu0 = 0.0f, cu1 = 0.0f;
    {
        const float* w0 = &sWc[lane * EMBED];
        const float* w1 = &sWc[(lane + 32) * EMBED];
        #pragma unroll
        for (int q = 0; q < EMBED; q++) {
            cu0 = fmaf(avg[q], w0[q], cu0);
            cu1 = fmaf(avg[q], w1[q], cu1);
        }
        cu0 = __fadd_rn(cu0, sbc[lane]);
        cu1 = __fadd_rn(cu1, sbc[lane + 32]);
    }

    // ---------------- phase B: 10-tick recurrence, 2 neurons/lane ----------
    uint32_t i0 = (uint32_t)(warp * HIDDEN + lane);
    uint32_t i1 = i0 + 32u;
    float v0 = 0.f, rf0 = 0.f, ac0 = 0.f;
    float v1 = 0.f, rf1 = 0.f, ac1 = 0.f;

    #pragma unroll
    for (int t = 0; t < TICKS; t++) {
        uint32_t nb0, fb0, nb1, fb1;
        tf4(K.nk[t], K.fk[t], i0, i1, nb0, fb0, nb1, fb1);
        tick_neuron(cu0, nb0, fb0, v0, rf0, ac0);
        tick_neuron(cu1, nb1, fb1, v1, rf1, ac1);
    }

    float s0 = __fdiv_rn(ac0, 10.0f);
    float s1 = __fdiv_rn(ac1, 10.0f);

    // ---------------- phase C: readout + spike write -----------------------
    spk_out[(size_t)warp * HIDDEN + lane]      = s0;
    spk_out[(size_t)warp * HIDDEN + lane + 32] = s1;

    #pragma unroll
    for (int cc = 0; cc < 4; cc++) {
        float p = __fadd_rn(__fmul_rn(s0, sWr[cc * HIDDEN + lane]),
                            __fmul_rn(s1, sWr[cc * HIDDEN + 32 + lane]));
        #pragma unroll
        for (int o = 16; o; o >>= 1)
            p = __fadd_rn(p, __shfl_xor_sync(0xffffffffu, p, o));
        if (lane == 0) logits[(size_t)warp * 4 + cc] = __fadd_rn(p, sbr[cc]);
    }
}

// ---------------------------------------------------------------------------
extern "C" void kernel_launch(void* const* d_in, const int* in_sizes, int n_in,
                              void* d_out, int out_size) {
    const int*   tokens = (const int*)d_in[0];
    const float* embed  = (const float*)d_in[1];
    const float* Wc     = (const float*)d_in[2];
    const float* bc     = (const float*)d_in[3];
    const float* Wr     = (const float*)d_in[4];
    const float* br     = (const float*)d_in[5];

    int B = in_sizes[0] / SEQLEN;

    // per-tick keys (JAX partitionable path), expanded key schedule
    KeysParam K;
    for (int t = 0; t < TICKS; t++) {
        uint32_t kt0, kt1, n0, n1, f0, f1;
        tf2x32_host(0u, 1u, 0u, (uint32_t)t, &kt0, &kt1);
        tf2x32_host(kt0, kt1, 0u, 0u, &n0, &n1);
        tf2x32_host(kt0, kt1, 0u, 1u, &f0, &f1);
        uint32_t n2 = n0 ^ n1 ^ 0x1BD11BDAu;
        uint32_t f2 = f0 ^ f1 ^ 0x1BD11BDAu;
        uint32_t ns[8] = { n0, n1, n2, n2 + 1u, n0 + 2u, n1 + 3u, n2 + 4u, n0 + 5u };
        uint32_t fs[8] = { f0, f1, f2, f2 + 1u, f0 + 2u, f1 + 3u, f2 + 4u, f0 + 5u };
        for (int j = 0; j < 8; j++) { K.nk[t][j] = ns[j]; K.fk[t][j] = fs[j]; }
    }

    float* out_f = (float*)d_out;
    float* spk_region = out_f + (size_t)B * 4;

    int blocks = (B * 32 + 255) / 256;   // one warp per row
    fused_kernel<<<blocks, 256>>>(tokens, embed, Wc, bc, Wr, br,
                                  out_f, spk_region, K, B);
}